// round 13
// baseline (speedup 1.0000x reference)
#include <cuda_runtime.h>
#include <cstdint>

#define NREL 500
#define NB   4096
#define DIM  256
#define CHUNK 12
#define ROWB 528            // smem bytes per half-row (512 data + 16 pad)
#define TROWS 16            // rows per pipeline tile
#define BUFB (TROWS * ROWB) // 8448 B per stage
#define NSTAGE 4

typedef unsigned long long ull;

// ---------------- device scratch ----------------
__device__ int g_offsets[NREL + 1];
__device__ int g_bucket[NB];
__device__ int g_order[NREL];     // relations sorted by bucket size, descending

// ---------------- fused preprocessing (1 CTA) ----------------
__global__ void k_prep(const int* __restrict__ rel32) {
    __shared__ int s_cnt[512];
    __shared__ int s_cur[NREL];
    __shared__ int s_chist[64];
    __shared__ int s_ccur[64];
    __shared__ int s_stride;
    int t = threadIdx.x;           // 512 threads

    if (t < 32) {
        unsigned b = __ballot_sync(0xFFFFFFFFu, rel32[2 * t + 1] != 0);
        if (t == 0) s_stride = b ? 1 : 2;   // int64 ids => odd words all zero
    }
    s_cnt[t] = 0;
    if (t < 64) s_chist[t] = 0;
    __syncthreads();
    int stride = s_stride;

    for (int i = t; i < NB; i += 512) {
        int r = rel32[i * stride];
        r = max(0, min(NREL - 1, r));
        atomicAdd(&s_cnt[r], 1);
    }
    __syncthreads();
    int c = s_cnt[t];
    int v = c;
    for (int off = 1; off < 512; off <<= 1) {
        int u = (t >= off) ? s_cnt[t - off] : 0;
        __syncthreads();
        v += u;
        s_cnt[t] = v;
        __syncthreads();
    }
    if (t < NREL) {
        g_offsets[t + 1] = v;
        s_cur[t] = v - c;
        atomicAdd(&s_chist[min(c, 63)], 1);
    }
    if (t == 0) g_offsets[0] = 0;
    __syncthreads();

    if (t == 0) {
        int acc = 0;
        for (int k = 63; k >= 0; --k) { s_ccur[k] = acc; acc += s_chist[k]; }
    }
    __syncthreads();
    if (t < NREL) {
        int p = atomicAdd(&s_ccur[min(c, 63)], 1);
        g_order[p] = t;
    }

    for (int i = t; i < NB; i += 512) {
        int r = rel32[i * stride];
        r = max(0, min(NREL - 1, r));
        int p = atomicAdd(&s_cur[r], 1);
        g_bucket[p] = i;
    }
}

// ---------------- helpers ----------------
__device__ __forceinline__ ull ffma2(ull a, ull b, ull c) {
    ull r;
    asm("fma.rn.f32x2 %0, %1, %2, %3;" : "=l"(r) : "l"(a), "l"(b), "l"(c));
    return r;
}
__device__ __forceinline__ ull dup2(float a) {
    ull r;
    asm("mov.b64 %0, {%1, %1};" : "=l"(r) : "f"(a));
    return r;
}
__device__ __forceinline__ ull addf2(ull a, ull b) {
    float2 x = *reinterpret_cast<float2*>(&a);
    float2 y = *reinterpret_cast<float2*>(&b);
    x.x += y.x; x.y += y.y;
    return *reinterpret_cast<ull*>(&x);
}
__device__ __forceinline__ uint32_t smem_u32(const void* p) {
    return (uint32_t)__cvta_generic_to_shared(p);
}
__device__ __forceinline__ void cp16(uint32_t dst, const void* src) {
    asm volatile("cp.async.cg.shared.global [%0], [%1], 16;" :: "r"(dst), "l"(src));
}
__device__ __forceinline__ void cp_commit() { asm volatile("cp.async.commit_group;"); }
template <int N>
__device__ __forceinline__ void cp_wait() { asm volatile("cp.async.wait_group %0;" :: "n"(N)); }

// stage one 16-row half-matrix tile into SMEM ring (512 granules of 16B, 2/thread)
__device__ __forceinline__ void issue_tile(const char* gM, uint32_t smbase, int tile, int t) {
#pragma unroll
    for (int g = t; g < 512; g += 256) {
        int row = g >> 5, c = g & 31;
        cp16(smbase + (uint32_t)(tile & 3) * BUFB + row * ROWB + c * 16,
             gM + (size_t)(tile * TROWS + row) * 1024 + c * 16);
    }
}

// one tile: 2 subrows/thread; transposed embeddings: 1 LDS.128 -> 4 samples -> 8 FFMA2
template <int NS>
__device__ __forceinline__ void compute_tile(const char* buf, int i, const float* s_e,
                                             int kh, int cg, ull* a0, ull* a1) {
#pragma unroll
    for (int sr = 0; sr < 2; ++sr) {
        int rl = sr * 8 + kh;
        ulonglong2 m = *reinterpret_cast<const ulonglong2*>(buf + rl * ROWB + cg * 16);
        int d = i * TROWS + rl;
        const float4* ep = reinterpret_cast<const float4*>(s_e + d * 12);
#pragma unroll
        for (int q = 0; q < NS / 4; ++q) {
            float4 e = ep[q];                  // LDS.128: 4 samples, dim d
            ull e0 = dup2(e.x), e1 = dup2(e.y), e2 = dup2(e.z), e3 = dup2(e.w);
            a0[4*q+0] = ffma2(e0, m.x, a0[4*q+0]); a1[4*q+0] = ffma2(e0, m.y, a1[4*q+0]);
            a0[4*q+1] = ffma2(e1, m.x, a0[4*q+1]); a1[4*q+1] = ffma2(e1, m.y, a1[4*q+1]);
            a0[4*q+2] = ffma2(e2, m.x, a0[4*q+2]); a1[4*q+2] = ffma2(e2, m.y, a1[4*q+2]);
            a0[4*q+3] = ffma2(e3, m.x, a0[4*q+3]); a1[4*q+3] = ffma2(e3, m.y, a1[4*q+3]);
        }
    }
}

template <int NS>
__device__ __forceinline__ void run_chunk(const char* gM, char* s_m, const float* s_e,
                                          ull* out64, int jbase, int n,
                                          int t, int kh, int cg, int h) {
    uint32_t smbase = smem_u32(s_m);
    issue_tile(gM, smbase, 0, t); cp_commit();
    issue_tile(gM, smbase, 1, t); cp_commit();
    issue_tile(gM, smbase, 2, t); cp_commit();

    ull a0[NS], a1[NS];
#pragma unroll
    for (int s = 0; s < NS; ++s) { a0[s] = 0ull; a1[s] = 0ull; }

    for (int i = 0; i < 14; ++i) {
        cp_wait<2>();
        __syncthreads();
        if (i < 13) { issue_tile(gM, smbase, i + 3, t); cp_commit(); }
        compute_tile<NS>(s_m + (i & 3) * BUFB, i, s_e, kh, cg, a0, a1);
    }
    cp_wait<1>(); __syncthreads();
    compute_tile<NS>(s_m + (14 & 3) * BUFB, 14, s_e, kh, cg, a0, a1);
    cp_wait<0>(); __syncthreads();
    compute_tile<NS>(s_m + (15 & 3) * BUFB, 15, s_e, kh, cg, a0, a1);

    // reduce over kh (8-lane groups share cg)
#pragma unroll
    for (int s = 0; s < NS; ++s) {
        a0[s] = addf2(a0[s], __shfl_down_sync(0xFFFFFFFFu, a0[s], 4));
        a1[s] = addf2(a1[s], __shfl_down_sync(0xFFFFFFFFu, a1[s], 4));
        a0[s] = addf2(a0[s], __shfl_down_sync(0xFFFFFFFFu, a0[s], 2));
        a1[s] = addf2(a1[s], __shfl_down_sync(0xFFFFFFFFu, a1[s], 2));
        a0[s] = addf2(a0[s], __shfl_down_sync(0xFFFFFFFFu, a0[s], 1));
        a1[s] = addf2(a1[s], __shfl_down_sync(0xFFFFFFFFu, a1[s], 1));
    }
    if (kh == 0) {
#pragma unroll
        for (int s = 0; s < NS; ++s)
            if (s < n) {
                ulonglong2 o; o.x = a0[s]; o.y = a1[s];
                *reinterpret_cast<ulonglong2*>(
                    out64 + (size_t)g_bucket[jbase + s] * 128 + h * 64 + cg * 2) = o;
            }
    }
}

// ---------------- main: CTA = (relation, column-half), 3 CTAs/SM ----------------
__global__ void __launch_bounds__(256, 3) k_main(const float* __restrict__ emb,
                                                 const float* __restrict__ mats,
                                                 float* __restrict__ out) {
    __shared__ float s_e[DIM * 12];                     // transposed, 12 KB
    __shared__ __align__(16) char s_m[NSTAGE * BUFB];   // 33792 B

    int r = g_order[blockIdx.x >> 1];     // big buckets first
    int h = blockIdx.x & 1;
    int begin = g_offsets[r];
    int end   = g_offsets[r + 1];
    if (begin == end) return;

    int t  = threadIdx.x;
    int kh = t & 7;           // row class (mod 8)
    int cg = t >> 3;          // 0..31: owns u64 cols h*64 + 2cg, 2cg+1

    const char* gM = reinterpret_cast<const char*>(mats) +
                     (size_t)r * (DIM * DIM * 4) + (size_t)h * 512;   // half offset
    ull* out64 = reinterpret_cast<ull*>(out);

    for (int base = begin; base < end; base += CHUNK) {
        int n = min(CHUNK, end - base);
        int nsr = (n + 3) & ~3;

        // coalesced read, transposed store: s_e[d*12 + s]
        for (int i = t; i < nsr * DIM; i += 256) {
            int s = i >> 8;
            int d = i & 255;
            float v = 0.0f;
            if (s < n) v = emb[(size_t)g_bucket[base + s] * DIM + d];
            s_e[d * 12 + s] = v;
        }
        __syncthreads();

        switch (nsr) {
            case 4:  run_chunk<4 >(gM, s_m, s_e, out64, base, n, t, kh, cg, h); break;
            case 8:  run_chunk<8 >(gM, s_m, s_e, out64, base, n, t, kh, cg, h); break;
            default: run_chunk<12>(gM, s_m, s_e, out64, base, n, t, kh, cg, h); break;
        }
        __syncthreads();
    }
}

// ---------------- launch ----------------
extern "C" void kernel_launch(void* const* d_in, const int* in_sizes, int n_in,
                              void* d_out, int out_size) {
    const float* emb = nullptr;
    const int* rel = nullptr;
    const float* mats = nullptr;

    for (int i = 0; i < n_in; ++i) {
        if (in_sizes[i] == NB)                     rel  = (const int*)d_in[i];
        else if (in_sizes[i] == NB * DIM)          emb  = (const float*)d_in[i];
        else if (in_sizes[i] == NREL * DIM * DIM)  mats = (const float*)d_in[i];
    }
    if (!emb  && n_in > 0) emb  = (const float*)d_in[0];
    if (!rel  && n_in > 1) rel  = (const int*)d_in[1];
    if (!mats && n_in > 2) mats = (const float*)d_in[2];

    float* out = (float*)d_out;

    k_prep<<<1, 512>>>(rel);
    k_main<<<NREL * 2, 256>>>(emb, mats, out);
}

// round 15
// speedup vs baseline: 1.0820x; 1.0820x over previous
#include <cuda_runtime.h>
#include <cstdint>

#define NREL 500
#define NB   4096
#define DIM  256
#define CHUNK 12
#define ESTR 260            // per-sample float stride in s_e (bank spread)
#define ROWB 272            // smem bytes per quarter-row (256 data + 16 pad)
#define TROWS 16            // rows per pipeline tile
#define BUFB (TROWS * ROWB) // 4352 B per stage
#define NSTAGE 5            // lookahead 4

typedef unsigned long long ull;

// ---------------- device scratch ----------------
__device__ int g_offsets[NREL + 1];
__device__ int g_bucket[NB];
__device__ int g_order[NREL];     // relations sorted by bucket size, descending

// ---------------- fused preprocessing (1 CTA) ----------------
__global__ void k_prep(const int* __restrict__ rel32) {
    __shared__ int s_cnt[512];
    __shared__ int s_cur[NREL];
    __shared__ int s_chist[64];
    __shared__ int s_ccur[64];
    __shared__ int s_stride;
    int t = threadIdx.x;           // 512 threads

    if (t < 32) {
        unsigned b = __ballot_sync(0xFFFFFFFFu, rel32[2 * t + 1] != 0);
        if (t == 0) s_stride = b ? 1 : 2;   // int64 ids => odd words all zero
    }
    s_cnt[t] = 0;
    if (t < 64) s_chist[t] = 0;
    __syncthreads();
    int stride = s_stride;

    for (int i = t; i < NB; i += 512) {
        int r = rel32[i * stride];
        r = max(0, min(NREL - 1, r));
        atomicAdd(&s_cnt[r], 1);
    }
    __syncthreads();
    int c = s_cnt[t];
    int v = c;
    for (int off = 1; off < 512; off <<= 1) {
        int u = (t >= off) ? s_cnt[t - off] : 0;
        __syncthreads();
        v += u;
        s_cnt[t] = v;
        __syncthreads();
    }
    if (t < NREL) {
        g_offsets[t + 1] = v;
        s_cur[t] = v - c;
        atomicAdd(&s_chist[min(c, 63)], 1);
    }
    if (t == 0) g_offsets[0] = 0;
    __syncthreads();

    if (t == 0) {
        int acc = 0;
        for (int k = 63; k >= 0; --k) { s_ccur[k] = acc; acc += s_chist[k]; }
    }
    __syncthreads();
    if (t < NREL) {
        int p = atomicAdd(&s_ccur[min(c, 63)], 1);
        g_order[p] = t;
    }

    for (int i = t; i < NB; i += 512) {
        int r = rel32[i * stride];
        r = max(0, min(NREL - 1, r));
        int p = atomicAdd(&s_cur[r], 1);
        g_bucket[p] = i;
    }
}

// ---------------- helpers ----------------
__device__ __forceinline__ ull ffma2(ull a, ull b, ull c) {
    ull r;
    asm("fma.rn.f32x2 %0, %1, %2, %3;" : "=l"(r) : "l"(a), "l"(b), "l"(c));
    return r;
}
__device__ __forceinline__ ull dup2(float a) {
    ull r;
    asm("mov.b64 %0, {%1, %1};" : "=l"(r) : "f"(a));
    return r;
}
__device__ __forceinline__ ull addf2(ull a, ull b) {
    float2 x = *reinterpret_cast<float2*>(&a);
    float2 y = *reinterpret_cast<float2*>(&b);
    x.x += y.x; x.y += y.y;
    return *reinterpret_cast<ull*>(&x);
}
__device__ __forceinline__ uint32_t smem_u32(const void* p) {
    return (uint32_t)__cvta_generic_to_shared(p);
}
__device__ __forceinline__ void cp16(uint32_t dst, const void* src) {
    asm volatile("cp.async.cg.shared.global [%0], [%1], 16;" :: "r"(dst), "l"(src));
}
__device__ __forceinline__ void cp_commit() { asm volatile("cp.async.commit_group;"); }
template <int N>
__device__ __forceinline__ void cp_wait() { asm volatile("cp.async.wait_group %0;" :: "n"(N)); }

// stage one 16-row quarter-matrix tile (256 granules of 16B, 2 per thread)
__device__ __forceinline__ void issue_tile(const char* gM, uint32_t smbase, int tile, int t) {
    uint32_t dst = smbase + (uint32_t)(tile % NSTAGE) * BUFB;
#pragma unroll
    for (int g = t; g < 256; g += 128) {
        int row = g >> 4, c = g & 15;
        cp16(dst + row * ROWB + c * 16,
             gM + (size_t)(tile * TROWS + row) * 1024 + c * 16);
    }
}

// one tile: 2 subrows/thread; R10-style broadcast LDS.32 emb + ALU dup + FFMA2
template <int NS>
__device__ __forceinline__ void compute_tile(const char* buf, int i, const float* s_e,
                                             int kh, int cg, ull* a0, ull* a1) {
#pragma unroll
    for (int sr = 0; sr < 2; ++sr) {
        int rl = sr * 8 + kh;
        ulonglong2 m = *reinterpret_cast<const ulonglong2*>(buf + rl * ROWB + cg * 16);
        int d = i * TROWS + rl;
        const float* se = s_e + d;
#pragma unroll
        for (int s = 0; s < NS; ++s) {
            ull e = dup2(se[s * ESTR]);        // LDS.32 broadcast (8 distinct d/warp)
            a0[s] = ffma2(e, m.x, a0[s]);
            a1[s] = ffma2(e, m.y, a1[s]);
        }
    }
}

template <int NS>
__device__ __forceinline__ void run_chunk(const char* gM, char* s_m, const float* s_e,
                                          ull* out64, int jbase, int n,
                                          int t, int kh, int cg, int q) {
    uint32_t smbase = smem_u32(s_m);
    issue_tile(gM, smbase, 0, t); cp_commit();
    issue_tile(gM, smbase, 1, t); cp_commit();
    issue_tile(gM, smbase, 2, t); cp_commit();
    issue_tile(gM, smbase, 3, t); cp_commit();

    ull a0[NS], a1[NS];
#pragma unroll
    for (int s = 0; s < NS; ++s) { a0[s] = 0ull; a1[s] = 0ull; }

    for (int i = 0; i < 12; ++i) {
        cp_wait<3>();
        __syncthreads();
        issue_tile(gM, smbase, i + 4, t); cp_commit();   // buf (i+4)%5=(i-1)%5: freed
        compute_tile<NS>(s_m + (i % NSTAGE) * BUFB, i, s_e, kh, cg, a0, a1);
    }
    cp_wait<3>(); __syncthreads();
    compute_tile<NS>(s_m + (12 % NSTAGE) * BUFB, 12, s_e, kh, cg, a0, a1);
    cp_wait<2>(); __syncthreads();
    compute_tile<NS>(s_m + (13 % NSTAGE) * BUFB, 13, s_e, kh, cg, a0, a1);
    cp_wait<1>(); __syncthreads();
    compute_tile<NS>(s_m + (14 % NSTAGE) * BUFB, 14, s_e, kh, cg, a0, a1);
    cp_wait<0>(); __syncthreads();
    compute_tile<NS>(s_m + (15 % NSTAGE) * BUFB, 15, s_e, kh, cg, a0, a1);

    // reduce over kh (8-lane groups share cg)
#pragma unroll
    for (int s = 0; s < NS; ++s) {
        a0[s] = addf2(a0[s], __shfl_down_sync(0xFFFFFFFFu, a0[s], 4));
        a1[s] = addf2(a1[s], __shfl_down_sync(0xFFFFFFFFu, a1[s], 4));
        a0[s] = addf2(a0[s], __shfl_down_sync(0xFFFFFFFFu, a0[s], 2));
        a1[s] = addf2(a1[s], __shfl_down_sync(0xFFFFFFFFu, a1[s], 2));
        a0[s] = addf2(a0[s], __shfl_down_sync(0xFFFFFFFFu, a0[s], 1));
        a1[s] = addf2(a1[s], __shfl_down_sync(0xFFFFFFFFu, a1[s], 1));
    }
    if (kh == 0) {
#pragma unroll
        for (int s = 0; s < NS; ++s)
            if (s < n) {
                ulonglong2 o; o.x = a0[s]; o.y = a1[s];
                *reinterpret_cast<ulonglong2*>(
                    out64 + (size_t)g_bucket[jbase + s] * 128 + q * 32 + cg * 2) = o;
            }
    }
}

// ---------------- main: CTA = (relation, quarter), 128 thr, 6 CTAs/SM ----------------
__global__ void __launch_bounds__(128, 6) k_main(const float* __restrict__ emb,
                                                 const float* __restrict__ mats,
                                                 float* __restrict__ out) {
    __shared__ float s_e[CHUNK * ESTR];                 // 12480 B
    __shared__ __align__(16) char s_m[NSTAGE * BUFB];   // 21760 B

    int r = g_order[blockIdx.x >> 2];     // big buckets first
    int q = blockIdx.x & 3;               // column quarter
    int begin = g_offsets[r];
    int end   = g_offsets[r + 1];
    if (begin == end) return;

    int t  = threadIdx.x;
    int kh = t & 7;           // row class (mod 8)
    int cg = t >> 3;          // 0..15: owns u64 cols q*32 + 2cg, 2cg+1

    const char* gM = reinterpret_cast<const char*>(mats) +
                     (size_t)r * (DIM * DIM * 4) + (size_t)q * 256;   // quarter offset
    ull* out64 = reinterpret_cast<ull*>(out);

    for (int base = begin; base < end; base += CHUNK) {
        int n = min(CHUNK, end - base);
        int nsr = (n + 3) & ~3;

        // stage embeddings, layout s_e[s*ESTR + d]
        for (int i = t; i < nsr * DIM; i += 128) {
            int s = i >> 8;
            int d = i & 255;
            float v = 0.0f;
            if (s < n) v = emb[(size_t)g_bucket[base + s] * DIM + d];
            s_e[s * ESTR + d] = v;
        }
        __syncthreads();

        switch (nsr) {
            case 4:  run_chunk<4 >(gM, s_m, s_e, out64, base, n, t, kh, cg, q); break;
            case 8:  run_chunk<8 >(gM, s_m, s_e, out64, base, n, t, kh, cg, q); break;
            default: run_chunk<12>(gM, s_m, s_e, out64, base, n, t, kh, cg, q); break;
        }
        __syncthreads();
    }
}

// ---------------- launch ----------------
extern "C" void kernel_launch(void* const* d_in, const int* in_sizes, int n_in,
                              void* d_out, int out_size) {
    const float* emb = nullptr;
    const int* rel = nullptr;
    const float* mats = nullptr;

    for (int i = 0; i < n_in; ++i) {
        if (in_sizes[i] == NB)                     rel  = (const int*)d_in[i];
        else if (in_sizes[i] == NB * DIM)          emb  = (const float*)d_in[i];
        else if (in_sizes[i] == NREL * DIM * DIM)  mats = (const float*)d_in[i];
    }
    if (!emb  && n_in > 0) emb  = (const float*)d_in[0];
    if (!rel  && n_in > 1) rel  = (const int*)d_in[1];
    if (!mats && n_in > 2) mats = (const float*)d_in[2];

    float* out = (float*)d_out;

    k_prep<<<1, 512>>>(rel);
    k_main<<<NREL * 4, 128>>>(emb, mats, out);
}